// round 9
// baseline (speedup 1.0000x reference)
#include <cuda_runtime.h>
#include <cuda_bf16.h>

// Dequantize: out[j] = codebooks[cb][code[g]][j%4] * scales[j/64]
//   g = j/4, cb = (g >= N_codes/2) ? 1 : 0   (codes buffer is [2, N/2] contiguous)
//
// Codebook: 2*256*4 fp32 = 8KB -> shared memory (512 float4 entries).
// Each thread: 1x int4 code load (4 codes), 4x SMEM float4 gathers,
//              1 scale load (16 outputs / thread, block=64 -> scale idx = t>>2),
//              4x float4 stores.

__global__ __launch_bounds__(256)
void dequant_kernel(const float4* __restrict__ codebooks,   // 512 x float4
                    const float*  __restrict__ scales,
                    const int4*   __restrict__ codes,        // N/4 int4
                    float4*       __restrict__ out,          // N float4 (numel/4)
                    int n_vec4,                              // N_codes / 4
                    int half_codes)                          // N_codes / 2
{
    __shared__ float4 cb[512];

    // Stage codebook into SMEM (8KB). 256 threads x 2 float4.
    #pragma unroll
    for (int i = threadIdx.x; i < 512; i += 256)
        cb[i] = codebooks[i];
    __syncthreads();

    int t = blockIdx.x * blockDim.x + threadIdx.x;
    if (t >= n_vec4) return;

    const int g0  = t << 2;                      // first code index
    const int off = (g0 >= half_codes) ? 256 : 0; // codebook select (uniform per int4)

    int4  c = codes[t];                          // coalesced 512B/warp
    float s = __ldg(&scales[t >> 2]);            // one block scale per 16 outputs

    float4 v0 = cb[c.x + off];
    float4 v1 = cb[c.y + off];
    float4 v2 = cb[c.z + off];
    float4 v3 = cb[c.w + off];

    float4 o0, o1, o2, o3;
    o0.x = v0.x * s; o0.y = v0.y * s; o0.z = v0.z * s; o0.w = v0.w * s;
    o1.x = v1.x * s; o1.y = v1.y * s; o1.z = v1.z * s; o1.w = v1.w * s;
    o2.x = v2.x * s; o2.y = v2.y * s; o2.z = v2.z * s; o2.w = v2.w * s;
    o3.x = v3.x * s; o3.y = v3.y * s; o3.z = v3.z * s; o3.w = v3.w * s;

    float4* op = out + (size_t)g0;
    op[0] = o0;
    op[1] = o1;
    op[2] = o2;
    op[3] = o3;
}

extern "C" void kernel_launch(void* const* d_in, const int* in_sizes, int n_in,
                              void* d_out, int out_size)
{
    // metadata order: codebooks (f32), scales (f32), codes (i32), rows (i32), columns (i32)
    const float4* codebooks = (const float4*)d_in[0];
    const float*  scales    = (const float*) d_in[1];
    const int4*   codes     = (const int4*)  d_in[2];
    float4*       out       = (float4*)      d_out;

    const int n_codes = in_sizes[2];     // 2 * numel / 8 = numel / 4
    const int half    = n_codes / 2;
    const int n_vec4  = n_codes / 4;

    const int threads = 256;
    const int blocks  = (n_vec4 + threads - 1) / threads;

    dequant_kernel<<<blocks, threads>>>(codebooks, scales, codes, out, n_vec4, half);
}

// round 10
// speedup vs baseline: 1.1118x; 1.1118x over previous
#include <cuda_runtime.h>
#include <cuda_bf16.h>

// Dequantize: out4[g] = codebooks[cb][code[g]] * scales[g/16]
//   cb = (g >= N_codes/2) ? 1 : 0   (codes buffer is [2, N/2] contiguous)
//
// One code per thread:
//   - code load:  LDG.32, fully coalesced (128B/warp)
//   - gather:     LDS.128 from 8KB SMEM codebook
//   - scale:      uniform across 16 lanes -> L1 broadcast
//   - store:      STG.128, 32 contiguous lanes = 512B coalesced (4 wavefronts, minimal)

__global__ __launch_bounds__(256)
void dequant_kernel(const float4* __restrict__ codebooks,   // 512 x float4
                    const float*  __restrict__ scales,
                    const int*    __restrict__ codes,        // N codes (i32)
                    float4*       __restrict__ out,          // N float4
                    int n_codes,
                    int half_codes)
{
    __shared__ float4 cb[512];

    #pragma unroll
    for (int i = threadIdx.x; i < 512; i += 256)
        cb[i] = codebooks[i];
    __syncthreads();

    int t = blockIdx.x * blockDim.x + threadIdx.x;
    if (t >= n_codes) return;

    const int off = (t >= half_codes) ? 256 : 0;   // uniform per warp

    int   c = __ldcs(&codes[t]);                   // read-once, coalesced
    float s = __ldcs(&scales[t >> 4]);             // 16-lane broadcast

    float4 v = cb[c + off];
    float4 o;
    o.x = v.x * s;
    o.y = v.y * s;
    o.z = v.z * s;
    o.w = v.w * s;

    __stcs(&out[(size_t)t], o);                    // write-once, fully coalesced
}

extern "C" void kernel_launch(void* const* d_in, const int* in_sizes, int n_in,
                              void* d_out, int out_size)
{
    // metadata order: codebooks (f32), scales (f32), codes (i32), rows, columns
    const float4* codebooks = (const float4*)d_in[0];
    const float*  scales    = (const float*) d_in[1];
    const int*    codes     = (const int*)   d_in[2];
    float4*       out       = (float4*)      d_out;

    const int n_codes = in_sizes[2];     // numel / 4  (both codebooks)
    const int half    = n_codes / 2;

    const int threads = 256;
    const int blocks  = (n_codes + threads - 1) / threads;

    dequant_kernel<<<blocks, threads>>>(codebooks, scales, codes, out, n_codes, half);
}

// round 11
// speedup vs baseline: 1.5360x; 1.3815x over previous
#include <cuda_runtime.h>
#include <cuda_bf16.h>

// Dequantize: out4[g] = codebooks[cb][code[g]] * scales[g/16]
//   cb = (g >= N_codes/2) ? 1 : 0   (codes buffer is [2, N/2] contiguous)
//
// 4 codes per thread, block-strided: idx = blockBase + tid + 256*k.
//   - all code loads / scale loads / stores fully coalesced per instruction
//   - 4 independent load->gather->store chains per thread (MLP=4) to
//     saturate the L1/LSU pipe (R9 showed L1=79% with MLP=1)

#define TPB   256
#define KPT   4   // codes per thread

__global__ __launch_bounds__(TPB)
void dequant_kernel(const float4* __restrict__ codebooks,   // 512 x float4
                    const float*  __restrict__ scales,
                    const int*    __restrict__ codes,        // N codes (i32)
                    float4*       __restrict__ out,          // N float4
                    int n_codes,
                    int half_codes)
{
    __shared__ float4 cb[512];

    #pragma unroll
    for (int i = threadIdx.x; i < 512; i += TPB)
        cb[i] = codebooks[i];
    __syncthreads();

    const int base = blockIdx.x * (TPB * KPT) + threadIdx.x;

    int   c[KPT];
    float s[KPT];
    bool  ok[KPT];

    #pragma unroll
    for (int k = 0; k < KPT; k++) {
        int idx = base + k * TPB;
        ok[k] = (idx < n_codes);
        if (ok[k]) {
            c[k] = __ldcs(&codes[idx]) + ((idx >= half_codes) ? 256 : 0);
            s[k] = __ldcs(&scales[idx >> 4]);
        }
    }

    float4 v[KPT];
    #pragma unroll
    for (int k = 0; k < KPT; k++)
        if (ok[k]) v[k] = cb[c[k]];

    #pragma unroll
    for (int k = 0; k < KPT; k++) {
        if (ok[k]) {
            float4 o;
            o.x = v[k].x * s[k];
            o.y = v[k].y * s[k];
            o.z = v[k].z * s[k];
            o.w = v[k].w * s[k];
            __stcs(&out[(size_t)(base + k * TPB)], o);
        }
    }
}

extern "C" void kernel_launch(void* const* d_in, const int* in_sizes, int n_in,
                              void* d_out, int out_size)
{
    // metadata order: codebooks (f32), scales (f32), codes (i32), rows, columns
    const float4* codebooks = (const float4*)d_in[0];
    const float*  scales    = (const float*) d_in[1];
    const int*    codes     = (const int*)   d_in[2];
    float4*       out       = (float4*)      d_out;

    const int n_codes = in_sizes[2];     // numel / 4  (both codebooks)
    const int half    = n_codes / 2;

    const int per_block = TPB * KPT;
    const int blocks    = (n_codes + per_block - 1) / per_block;

    dequant_kernel<<<blocks, TPB>>>(codebooks, scales, codes, out, n_codes, half);
}